// round 9
// baseline (speedup 1.0000x reference)
#include <cuda_runtime.h>

// ScatterLoss — per-class contrastive hinge loss.
// d_in[0] = output [N, D] float32 (N=65536, D=512)
// d_in[1] = label_id [N] int32
// out     = scalar float32
//
// loss = (1/N) * sum_k cnt_k * relu(1 - || s_k/c_k - (T - s_k)/(N - c_k) + 1e-6 ||_2)^2

#define NCLS 512
#define DDIM 512
#define CPC  2            // classes per CTA in the fused kernel
#define LCAP 384          // per-class list cap (mean 128, sigma 11.3 -> 22 sigma)
#define PAD  32           // floats per 128B line — atomic-target padding

// Zeroed each replay by one 64KB memset node.
struct ZeroBlk {
    float d2[NCLS * PAD];
    unsigned int ticket;
};
static __device__ ZeroBlk g_z;

static __device__ int   g_cnt[NCLS];            // written by fused kernel
static __device__ float g_sums[NCLS][DDIM];     // full class sums (unsplit)

// ---------------------------------------------------------------------------
// K1 (fused scan + gather): 256 CTAs x 256 threads, 2 classes per CTA.
// Phase A: scan the 256KB label array (L1/L2 resident; 64 int4 per thread),
//          compact matching row indices into smem lists; counts computed
//          locally — no global atomics, no scatter kernel, no dependency.
// Phase B: per class, gather its ~128 rows (2KB coalesced float4 reads,
//          __ldcs evict-first) and reduce to g_sums[k].
// DRAM-bound on the mandatory single 128MB read; the scan hides in L2.
// ---------------------------------------------------------------------------
__global__ void __launch_bounds__(256) k_fused_sum(const float* __restrict__ out,
                                                   const int* __restrict__ lab,
                                                   int N)
{
    __shared__ int    slist[CPC][LCAP];
    __shared__ int    scnt[CPC];
    __shared__ float4 sh[128];

    int t  = threadIdx.x;
    int k0 = blockIdx.x * CPC;

    if (t < CPC) scnt[t] = 0;
    __syncthreads();

    // --- Phase A: label scan (N = 65536 -> 16384 int4 -> 64 per thread) ---
    const int4* lab4 = (const int4*)lab;
    int nv4 = N >> 2;
    #pragma unroll 8
    for (int it = t; it < nv4; it += 256) {
        int4 v = __ldg(lab4 + it);
        int i0 = it << 2;
        #pragma unroll
        for (int l = 0; l < 4; l++) {
            int kk = (l == 0) ? v.x : (l == 1) ? v.y : (l == 2) ? v.z : v.w;
            int d  = kk - k0;
            if ((unsigned)d < CPC) {
                int p = atomicAdd(&scnt[d], 1);
                if (p < LCAP) slist[d][p] = i0 + l;
            }
        }
    }
    __syncthreads();

    if (t < CPC) g_cnt[k0 + t] = scnt[t];   // true counts for the loss math

    // --- Phase B: gather + reduce, one class at a time ---
    int q   = t & 127;        // float4 column
    int sub = t >> 7;         // row-subset 0/1

    #pragma unroll
    for (int m = 0; m < CPC; m++) {
        int nk = min(scnt[m], LCAP);
        float4 acc = make_float4(0.f, 0.f, 0.f, 0.f);
        #pragma unroll 8
        for (int j = sub; j < nk; j += 2) {
            const float4* row = (const float4*)(out + (size_t)slist[m][j] * DDIM);
            float4 v = __ldcs(row + q);      // read-once: evict-first
            acc.x += v.x; acc.y += v.y; acc.z += v.z; acc.w += v.w;
        }
        if (sub == 1) sh[q] = acc;
        __syncthreads();
        if (sub == 0) {
            float4 b = sh[q];
            acc.x += b.x; acc.y += b.y; acc.z += b.z; acc.w += b.w;
            ((float4*)g_sums[k0 + m])[q] = acc;
        }
        __syncthreads();
    }
}

// ---------------------------------------------------------------------------
// K2: fused grand-total + per-class d^2 partials + last-CTA finalize.
// 32 CTAs x 256 threads; CTA owns 4 float4-columns, thread owns 2 classes.
// 8 L2-resident float4 loads per thread; one d^2 atomicAdd per (class,CTA)
// (16K padded atomics). Last CTA does hinge + count-weighted mean.
// ---------------------------------------------------------------------------
__global__ void __launch_bounds__(256) k_colloss(float* __restrict__ outp, float fN)
{
    __shared__ float4 red[256];
    __shared__ unsigned int s_tkt;
    int t   = threadIdx.x;
    int cg0 = blockIdx.x * 4;          // first float4 column of this CTA

    float4 s[2][4];
    #pragma unroll
    for (int m = 0; m < 2; m++) {
        int k = t + m * 256;
        #pragma unroll
        for (int cc = 0; cc < 4; cc++)
            s[m][cc] = ((const float4*)g_sums[k])[cg0 + cc];
    }

    // grand totals for the CTA's 4 columns
    float4 T[4];
    #pragma unroll
    for (int cc = 0; cc < 4; cc++) {
        float4 x;
        x.x = s[0][cc].x + s[1][cc].x; x.y = s[0][cc].y + s[1][cc].y;
        x.z = s[0][cc].z + s[1][cc].z; x.w = s[0][cc].w + s[1][cc].w;
        red[t] = x;
        __syncthreads();
        #pragma unroll
        for (int sh = 128; sh > 0; sh >>= 1) {
            if (t < sh) {
                float4 b = red[t + sh];
                red[t].x += b.x; red[t].y += b.y; red[t].z += b.z; red[t].w += b.w;
            }
            __syncthreads();
        }
        T[cc] = red[0];
        __syncthreads();
    }

    #pragma unroll
    for (int m = 0; m < 2; m++) {
        int k = t + m * 256;
        int c = g_cnt[k];
        if (c > 0) {
            float fc  = (float)c;
            float ip  = 1.f / fc;
            float in_ = 1.f / (fN - fc);
            float p = 0.f;
            #pragma unroll
            for (int cc = 0; cc < 4; cc++) {
                float dx = s[m][cc].x * ip - (T[cc].x - s[m][cc].x) * in_ + 1e-6f;
                float dy = s[m][cc].y * ip - (T[cc].y - s[m][cc].y) * in_ + 1e-6f;
                float dz = s[m][cc].z * ip - (T[cc].z - s[m][cc].z) * in_ + 1e-6f;
                float dw = s[m][cc].w * ip - (T[cc].w - s[m][cc].w) * in_ + 1e-6f;
                p += dx * dx + dy * dy + dz * dz + dw * dw;
            }
            atomicAdd(&g_z.d2[k * PAD], p);
        }
    }

    // last-CTA finalize
    __threadfence();
    __syncthreads();
    if (t == 0) s_tkt = atomicAdd(&g_z.ticket, 1u);
    __syncthreads();
    if (s_tkt == (unsigned)(gridDim.x - 1)) {
        float w = 0.f;
        #pragma unroll
        for (int m = 0; m < 2; m++) {
            int k = t + m * 256;
            int c = g_cnt[k];
            if (c > 0) {
                float dist = sqrtf(g_z.d2[k * PAD]);
                float mg = fmaxf(1.0f - dist, 0.f);   // MARGIN = 1.0
                w += (float)c * mg * mg;
            }
        }
        ((float*)red)[t] = w;
        __syncthreads();
        #pragma unroll
        for (int sh = 128; sh > 0; sh >>= 1) {
            if (t < sh) ((float*)red)[t] += ((float*)red)[t + sh];
            __syncthreads();
        }
        if (t == 0) outp[0] = ((float*)red)[0] / fN;
    }
}

// ---------------------------------------------------------------------------
extern "C" void kernel_launch(void* const* d_in, const int* in_sizes, int n_in,
                              void* d_out, int out_size)
{
    const float* output = (const float*)d_in[0];
    const int*   label  = (const int*)d_in[1];
    int N = in_sizes[1];

    void* zptr = nullptr;
    cudaGetSymbolAddress(&zptr, g_z);            // host-side query; capture-safe
    cudaMemsetAsync(zptr, 0, sizeof(ZeroBlk));   // d2 partials + ticket

    k_fused_sum<<<NCLS / CPC, 256>>>(output, label, N);
    k_colloss<<<(DDIM / 4) / 4, 256>>>((float*)d_out, (float)N);
}

// round 10
// speedup vs baseline: 1.3956x; 1.3956x over previous
#include <cuda_runtime.h>

// ScatterLoss — per-class contrastive hinge loss.
// d_in[0] = output [N, D] float32 (N=65536, D=512)
// d_in[1] = label_id [N] int32
// out     = scalar float32
//
// loss = (1/N) * sum_k cnt_k * relu(1 - || s_k/c_k - (T - s_k)/(N - c_k) + 1e-6 ||_2)^2

#define NCLS 512
#define DDIM 512
#define NF4  (DDIM / 4)   // 128 float4 columns
#define CAP  1024         // max rows per class (counts ~128±11)
#define NSPL 4            // class split factor for the streaming kernel
#define PAD  32           // ints per 128B line — atomic-target padding

// Zeroed each replay by one memset node (0 bits == 0.0f == 0).
struct ZeroBlk {
    int   cnt[NCLS * PAD];
    float d2[NCLS * PAD];
    unsigned int ticket;
};
static __device__ ZeroBlk g_z;

static __device__ int   g_idx[NCLS * CAP];
static __device__ float g_sumsp[NSPL][NCLS][DDIM];   // per-quarter class sums

// ---------------------------------------------------------------------------
// K1: one-phase counting-sort scatter, int4-vectorized.
// 64 CTAs x 256 threads, 4 labels per thread: one label load feeds 4
// independent atomic->store chains that overlap. Padded counters spread the
// 65K atomics over 512 distinct 128B lines (all L2 partitions).
// ---------------------------------------------------------------------------
__global__ void __launch_bounds__(256) k_scatter(const int* __restrict__ lab, int N)
{
    int t  = blockIdx.x * blockDim.x + threadIdx.x;   // 16384 threads
    if (t >= (N >> 2)) return;
    int4 v = __ldg((const int4*)lab + t);
    int i0 = t << 2;

    int k, p;
    k = v.x; if ((unsigned)k < NCLS) { p = atomicAdd(&g_z.cnt[k * PAD], 1); if (p < CAP) g_idx[k * CAP + p] = i0;     }
    k = v.y; if ((unsigned)k < NCLS) { p = atomicAdd(&g_z.cnt[k * PAD], 1); if (p < CAP) g_idx[k * CAP + p] = i0 + 1; }
    k = v.z; if ((unsigned)k < NCLS) { p = atomicAdd(&g_z.cnt[k * PAD], 1); if (p < CAP) g_idx[k * CAP + p] = i0 + 2; }
    k = v.w; if ((unsigned)k < NCLS) { p = atomicAdd(&g_z.cnt[k * PAD], 1); if (p < CAP) g_idx[k * CAP + p] = i0 + 3; }
}

// ---------------------------------------------------------------------------
// K2: per-class partial sums. Four CTAs per class (contiguous quarters of
// the row list). Index words load warp-uniform (broadcast); row data is read
// exactly once (__ldcs evict-first). 2KB coalesced float4 row reads,
// unroll 8 for MLP. Reads the full 128 MB matrix once -> HBM bound.
// ---------------------------------------------------------------------------
__global__ void __launch_bounds__(128) k_class_sum_q(const float* __restrict__ out)
{
    int k  = blockIdx.x >> 2;
    int h  = blockIdx.x & 3;
    int nk = min(g_z.cnt[k * PAD], CAP);
    int j0 = (h * nk) >> 2;
    int j1 = ((h + 1) * nk) >> 2;
    int nj = j1 - j0;

    const int* idx = g_idx + k * CAP + j0;
    int q = threadIdx.x;  // float4 column 0..127

    float4 acc = make_float4(0.f, 0.f, 0.f, 0.f);
    #pragma unroll 8
    for (int j = 0; j < nj; j++) {
        int r = __ldg(idx + j);                       // uniform -> broadcast
        const float4* row = (const float4*)(out + (size_t)r * DDIM);
        float4 v = __ldcs(row + q);                   // read-once: evict-first
        acc.x += v.x; acc.y += v.y; acc.z += v.z; acc.w += v.w;
    }
    ((float4*)g_sumsp[h][k])[q] = acc;
}

// ---------------------------------------------------------------------------
// K3: fused grand-total + per-class d^2 partials + last-CTA finalize.
// 32 CTAs x 256 threads; CTA owns 4 float4-columns, thread owns 2 classes.
// All 4 columns reduced in ONE tree pass (8 syncs, not 32). One d^2
// atomicAdd per (class, CTA) = 16K padded atomics. Last CTA finishes the
// hinge + count-weighted mean and writes the scalar.
// ---------------------------------------------------------------------------
__global__ void __launch_bounds__(256) k_colloss(float* __restrict__ outp, float fN)
{
    __shared__ float4 red[4][256];
    __shared__ unsigned int s_tkt;
    int t   = threadIdx.x;
    int cg0 = blockIdx.x * 4;          // first float4 column of this CTA

    // fold the 4 quarter-sums for 2 classes x 4 columns
    float4 s[2][4];
    #pragma unroll
    for (int m = 0; m < 2; m++) {
        int k = t + m * 256;
        #pragma unroll
        for (int cc = 0; cc < 4; cc++) {
            float4 a = make_float4(0.f, 0.f, 0.f, 0.f);
            #pragma unroll
            for (int h = 0; h < NSPL; h++) {
                float4 v = ((const float4*)g_sumsp[h][k])[cg0 + cc];
                a.x += v.x; a.y += v.y; a.z += v.z; a.w += v.w;
            }
            s[m][cc] = a;
        }
    }

    // grand totals for all 4 columns in one tree pass
    #pragma unroll
    for (int cc = 0; cc < 4; cc++) {
        float4 x;
        x.x = s[0][cc].x + s[1][cc].x; x.y = s[0][cc].y + s[1][cc].y;
        x.z = s[0][cc].z + s[1][cc].z; x.w = s[0][cc].w + s[1][cc].w;
        red[cc][t] = x;
    }
    __syncthreads();
    #pragma unroll
    for (int sh = 128; sh > 0; sh >>= 1) {
        if (t < sh) {
            #pragma unroll
            for (int cc = 0; cc < 4; cc++) {
                float4 b = red[cc][t + sh];
                red[cc][t].x += b.x; red[cc][t].y += b.y;
                red[cc][t].z += b.z; red[cc][t].w += b.w;
            }
        }
        __syncthreads();
    }
    float4 T[4];
    #pragma unroll
    for (int cc = 0; cc < 4; cc++) T[cc] = red[cc][0];

    // per-class d^2 contribution over this CTA's 16 dims -> one atomic each
    #pragma unroll
    for (int m = 0; m < 2; m++) {
        int k = t + m * 256;
        int c = g_z.cnt[k * PAD];
        if (c > 0) {
            float fc  = (float)c;
            float ip  = 1.f / fc;
            float in_ = 1.f / (fN - fc);
            float p = 0.f;
            #pragma unroll
            for (int cc = 0; cc < 4; cc++) {
                float dx = s[m][cc].x * ip - (T[cc].x - s[m][cc].x) * in_ + 1e-6f;
                float dy = s[m][cc].y * ip - (T[cc].y - s[m][cc].y) * in_ + 1e-6f;
                float dz = s[m][cc].z * ip - (T[cc].z - s[m][cc].z) * in_ + 1e-6f;
                float dw = s[m][cc].w * ip - (T[cc].w - s[m][cc].w) * in_ + 1e-6f;
                p += dx * dx + dy * dy + dz * dz + dw * dw;
            }
            atomicAdd(&g_z.d2[k * PAD], p);
        }
    }

    // last-CTA finalize
    __threadfence();
    __syncthreads();
    if (t == 0) s_tkt = atomicAdd(&g_z.ticket, 1u);
    __syncthreads();
    if (s_tkt == (unsigned)(gridDim.x - 1)) {
        float w = 0.f;
        #pragma unroll
        for (int m = 0; m < 2; m++) {
            int k = t + m * 256;
            int c = g_z.cnt[k * PAD];
            if (c > 0) {
                float dist = sqrtf(g_z.d2[k * PAD]);
                float mg = fmaxf(1.0f - dist, 0.f);   // MARGIN = 1.0
                w += (float)c * mg * mg;
            }
        }
        float* fr = (float*)&red[0][0];
        fr[t] = w;
        __syncthreads();
        #pragma unroll
        for (int sh = 128; sh > 0; sh >>= 1) {
            if (t < sh) fr[t] += fr[t + sh];
            __syncthreads();
        }
        if (t == 0) outp[0] = fr[0] / fN;
    }
}

// ---------------------------------------------------------------------------
extern "C" void kernel_launch(void* const* d_in, const int* in_sizes, int n_in,
                              void* d_out, int out_size)
{
    const float* output = (const float*)d_in[0];
    const int*   label  = (const int*)d_in[1];
    int N = in_sizes[1];

    void* zptr = nullptr;
    cudaGetSymbolAddress(&zptr, g_z);            // host-side query; capture-safe
    cudaMemsetAsync(zptr, 0, sizeof(ZeroBlk));   // counters + d2 + ticket

    k_scatter<<<(N / 4 + 255) / 256, 256>>>(label, N);
    k_class_sum_q<<<NCLS * NSPL, 128>>>(output);
    k_colloss<<<NF4 / 4, 256>>>((float*)d_out, (float)N);
}